// round 14
// baseline (speedup 1.0000x reference)
#include <cuda_runtime.h>
#include <cuda_fp16.h>
#include <cstdint>
#include <math.h>

// Problem constants
#define Bb 8
#define Cc 1152
#define Hh 32
#define Ww 32
#define Nn 1024   // H*W
#define IBLK 64   // row-blocks per batch in k_row2 (Nn / ROWS_PER_BLK)

// ---------------- scratch (static device globals: allowed) ----------------
__device__ __align__(16) float g_alpha[Bb * Nn];
__device__ __align__(16) float g_beta [Bb * Nn];
__device__ __align__(16) float g_gamma[Bb * Nn];
__device__ __align__(16) float g_part [(size_t)IBLK * Bb * Nn]; // partial column sums
__device__ __align__(16) float g_cinv [Bb * Nn];                // 1 / csum
__device__ __align__(16) float g_colsum[Bb * Cc];               // colsum_c = sum_j F[c,j]
__device__ __align__(16) __half g_U[(size_t)Bb * Nn * Nn];      // u = 1 - exp(-s), fp16
__device__ __align__(16) __half g_F[(size_t)Bb * Cc * Nn];      // F = f_src / csum, fp16

// ======================= generic-PTX helpers ===============================
__device__ __forceinline__ uint32_t smem_to_u32(const void* p) {
    uint32_t a;
    asm("{ .reg .u64 t; cvta.to.shared.u64 t, %1; cvt.u32.u64 %0, t; }" : "=r"(a) : "l"(p));
    return a;
}
__device__ __forceinline__ void cp16(uint32_t s, const void* g) {
    asm volatile("cp.async.cg.shared.global [%0], [%1], 16;" :: "r"(s), "l"(g));
}
#define CP_COMMIT() asm volatile("cp.async.commit_group;" ::: "memory")
#define CP_WAIT(n)  asm volatile("cp.async.wait_group %0;" :: "n"(n) : "memory")

__device__ __forceinline__ void ldsm_x4(uint32_t* r, uint32_t addr) {
    asm volatile("ldmatrix.sync.aligned.m8n8.x4.shared.b16 {%0,%1,%2,%3}, [%4];"
                 : "=r"(r[0]), "=r"(r[1]), "=r"(r[2]), "=r"(r[3]) : "r"(addr));
}
__device__ __forceinline__ void mma16816h(float* c, const uint32_t* a, const uint32_t* b) {
    asm volatile(
        "mma.sync.aligned.m16n8k16.row.col.f32.f16.f16.f32 "
        "{%0,%1,%2,%3}, {%4,%5,%6,%7}, {%8,%9}, {%0,%1,%2,%3};"
        : "+f"(c[0]), "+f"(c[1]), "+f"(c[2]), "+f"(c[3])
        : "r"(a[0]), "r"(a[1]), "r"(a[2]), "r"(a[3]), "r"(b[0]), "r"(b[1]));
}

// ---------------- kernel 1: fundamental matrix + per-line coefficients ----
__global__ void k_coef(const float* __restrict__ K1, const float* __restrict__ K2,
                       const float* __restrict__ R,  const float* __restrict__ T)
{
    int b = blockIdx.x;
    __shared__ float F[9];
    if (threadIdx.x == 0) {
        const float* k1 = K1 + b * 9;
        const float* k2 = K2 + b * 9;
        const float* r  = R  + b * 9;
        const float* tv = T  + b * 3;
        float t0 = tv[0], t1 = tv[1], t2 = tv[2];
        float E[9];
        #pragma unroll
        for (int c = 0; c < 3; c++) {
            float r0 = r[0 * 3 + c], r1 = r[1 * 3 + c], r2 = r[2 * 3 + c];
            E[0 * 3 + c] = -t2 * r1 + t1 * r2;
            E[1 * 3 + c] =  t2 * r0 - t0 * r2;
            E[2 * 3 + c] = -t1 * r0 + t0 * r1;
        }
        float fx2 = k2[0], fy2 = k2[4], cx2 = k2[2], cy2 = k2[5];
        float M[9];
        #pragma unroll
        for (int c = 0; c < 3; c++) {
            M[0 * 3 + c] = E[0 * 3 + c] / fx2;
            M[1 * 3 + c] = E[1 * 3 + c] / fy2;
            M[2 * 3 + c] = -cx2 / fx2 * E[0 * 3 + c] - cy2 / fy2 * E[1 * 3 + c] + E[2 * 3 + c];
        }
        float fx1 = k1[0], fy1 = k1[4], cx1 = k1[2], cy1 = k1[5];
        #pragma unroll
        for (int rr = 0; rr < 3; rr++) {
            float m0 = M[rr * 3 + 0], m1 = M[rr * 3 + 1], m2 = M[rr * 3 + 2];
            F[rr * 3 + 0] = m0 / fx1;
            F[rr * 3 + 1] = m1 / fy1;
            F[rr * 3 + 2] = -cx1 / fx1 * m0 - cy1 / fy1 * m1 + m2;
        }
    }
    __syncthreads();
    for (int j = threadIdx.x; j < Nn; j += blockDim.x) {
        float x = (float)(j / Ww);
        float y = (float)(j % Ww);
        float l0 = F[0] * x + F[1] * y + F[2];
        float l1 = F[3] * x + F[4] * y + F[5];
        float l2 = F[6] * x + F[7] * y + F[8];
        float ap = l0 / l2;
        float bp = l1 / l2;
        float rn = rsqrtf(ap * ap + bp * bp);
        g_alpha[b * Nn + j] = ap * rn;
        g_beta [b * Nn + j] = bp * rn;
        g_gamma[b * Nn + j] = rn;
    }
}

// ---------------- kernel 2: fused row-softmax -> u = 1-exp(-s) fp16 ------
#define ROWS_PER_BLK 16
__global__ void __launch_bounds__(256) k_row2()
{
    int b  = blockIdx.y;
    int ib = blockIdx.x;
    int i0 = ib * ROWS_PER_BLK;
    const float* al = g_alpha + b * Nn;
    const float* be = g_beta  + b * Nn;
    const float* ga = g_gamma + b * Nn;
    __half* Up = g_U + (size_t)b * Nn * Nn;

    __shared__ float redm[8];
    __shared__ float redz[8];

    float A4[4], B4[4], G4[4];
    float cacc[4];
    #pragma unroll
    for (int k = 0; k < 4; k++) {
        int j = threadIdx.x + k * 256;
        A4[k] = al[j]; B4[k] = be[j]; G4[k] = ga[j];
        cacc[k] = 0.0f;
    }

    for (int r = 0; r < ROWS_PER_BLK; r++) {
        int i = i0 + r;
        float x = (float)(i / Ww);
        float y = (float)(i % Ww);
        float v[4];
        float m = -1e30f;
        #pragma unroll
        for (int k = 0; k < 4; k++) {
            v[k] = 5.0f * fabsf(fmaf(A4[k], x, fmaf(B4[k], y, G4[k])));
            m = fmaxf(m, v[k]);
        }
        #pragma unroll
        for (int o = 16; o; o >>= 1) m = fmaxf(m, __shfl_xor_sync(0xffffffffu, m, o));
        if ((threadIdx.x & 31) == 0) redm[threadIdx.x >> 5] = m;
        __syncthreads();
        float bm = redm[0];
        #pragma unroll
        for (int w = 1; w < 8; w++) bm = fmaxf(bm, redm[w]);

        float e1[4];
        float z = 0.0f;
        #pragma unroll
        for (int k = 0; k < 4; k++) { e1[k] = __expf(v[k] - bm); z += e1[k]; }
        #pragma unroll
        for (int o = 16; o; o >>= 1) z += __shfl_xor_sync(0xffffffffu, z, o);
        if ((threadIdx.x & 31) == 0) redz[threadIdx.x >> 5] = z;
        __syncthreads();
        float bz = 0.0f;
        #pragma unroll
        for (int w = 0; w < 8; w++) bz += redz[w];
        float inv = 1.0f / bz;

        size_t rowoff = (size_t)i * Nn;   // batch offset lives in Up pointer
        #pragma unroll
        for (int k = 0; k < 4; k++) {
            float s = e1[k] * inv;               // row-softmax value in (0,1]
            float e = __expf(-s);                // column-softmax numerator (shift 0)
            cacc[k] += e;
            float u = 1.0f - e;                  // GEMM operand: out = colsum - U@F^T
            int j = threadIdx.x + k * 256;
            Up[rowoff + j] = __float2half_rn(u);
        }
    }

    size_t poff = ((size_t)(b * IBLK + ib)) * Nn;
    #pragma unroll
    for (int k = 0; k < 4; k++)
        g_part[poff + threadIdx.x + k * 256] = cacc[k];
}

// ---------------- kernel 2b: cinv = 1 / sum_ib part ------------------------
__global__ void k_cinv()
{
    int i = blockIdx.x * blockDim.x + threadIdx.x;
    if (i >= Bb * Nn) return;
    int b = i / Nn, j = i % Nn;
    float s = 0.0f;
    #pragma unroll 8
    for (int ib = 0; ib < IBLK; ib++)
        s += g_part[((size_t)(b * IBLK + ib)) * Nn + j];
    g_cinv[i] = 1.0f / s;
}

// ---------------- kernel 3: F = f/csum -> fp16; colsum_c = sum_j F (fp32) --
__global__ void __launch_bounds__(256) k_conv_f(const float* __restrict__ f)
{
    int b  = blockIdx.y;
    int c0 = blockIdx.x * 4;
    int tid = threadIdx.x;
    const float* ci = g_cinv + b * Nn + tid * 4;
    float cv0 = ci[0], cv1 = ci[1], cv2 = ci[2], cv3 = ci[3];
    __shared__ float red[8];

    #pragma unroll
    for (int r = 0; r < 4; r++) {
        int c = c0 + r;
        size_t rowbase = ((size_t)(b * Cc + c)) * Nn;
        float4 v = *(const float4*)(f + rowbase + tid * 4);
        v.x *= cv0; v.y *= cv1; v.z *= cv2; v.w *= cv3;

        uint32_t w0 = (uint32_t)__half_as_ushort(__float2half_rn(v.x)) |
                      ((uint32_t)__half_as_ushort(__float2half_rn(v.y)) << 16);
        uint32_t w1 = (uint32_t)__half_as_ushort(__float2half_rn(v.z)) |
                      ((uint32_t)__half_as_ushort(__float2half_rn(v.w)) << 16);
        uint2 pk; pk.x = w0; pk.y = w1;
        *(uint2*)(g_F + rowbase + tid * 4) = pk;

        float sm = (v.x + v.y) + (v.z + v.w);   // fp32 colsum contribution
        #pragma unroll
        for (int o = 16; o; o >>= 1) sm += __shfl_xor_sync(0xffffffffu, sm, o);
        if ((tid & 31) == 0) red[tid >> 5] = sm;
        __syncthreads();
        if (tid == 0) {
            float t = 0.0f;
            #pragma unroll
            for (int w = 0; w < 8; w++) t += red[w];
            g_colsum[b * Cc + c] = t;
        }
        __syncthreads();
    }
}

// ---------------- kernel 4: fp16 mma GEMM, out = colsum - U @ F^T ---------
// Tile M=128, N=128, K in 16 stages of 64; 3-slot cp.async pipeline.
// NEW: register-level fragment double-buffering — each kk's LDSMs are issued
// one iteration ahead of the MMAs that consume them, so the LDSM->MMA
// dependency never stalls the warp and the smem and tensor pipes overlap.
// Costs ~48 extra regs -> occupancy 1 CTA/SM (acceptable: each warp alone
// now keeps both pipes fed; prefetch-2 cp.async covers global latency).
#define TILE_B   16384          // one 128x64 fp16 tile (swizzled, 128B rows)
#define STAGE_B  (2 * TILE_B)   // U, F
#define NSLOT    3
#define GEMM_SMEM (NSLOT * STAGE_B) // 98304
#define NSTAGE   (Nn / 64)      // 16

__global__ void __launch_bounds__(256, 1) k_gemm_mma(float* __restrict__ out)
{
    extern __shared__ char smem[];
    const uint32_t sb = smem_to_u32(smem);
    const int tid  = threadIdx.x;
    const int wid  = tid >> 5;
    const int lane = tid & 31;
    const int b    = blockIdx.z;
    const int n0   = blockIdx.x * 128;   // c tile
    const int m0   = blockIdx.y * 128;   // i tile

    const __half* Up = g_U + (size_t)b * Nn * Nn;
    const __half* Fp = g_F + (size_t)b * Cc * Nn;

    // producer chunk mapping: 1024 16B chunks per tile, 4 per thread
    uint32_t p_soff[4];
    uint32_t p_row[4];
    #pragma unroll
    for (int q = 0; q < 4; q++) {
        int id  = tid + q * 256;
        int row = id >> 3;
        int c   = id & 7;
        p_row[q]  = row;
        p_soff[q] = (uint32_t)(row * 128 + ((16 * c) ^ ((row & 7) << 4)));
    }

    // MMA thread geometry
    const int warp_m = wid & 1;        // 0..1
    const int warp_n = wid >> 1;       // 0..3
    const int g  = lane >> 3;          // ldmatrix address group 0..3
    const int r  = lane & 7;
    uint32_t arow[4], brow[2];
    #pragma unroll
    for (int mt = 0; mt < 4; mt++)
        arow[mt] = (uint32_t)((warp_m * 64 + mt * 16 + (g & 1) * 8 + r) * 128);
    #pragma unroll
    for (int p = 0; p < 2; p++)
        brow[p] = (uint32_t)((warp_n * 32 + p * 16 + (g >> 1) * 8 + r) * 128);
    const uint32_t ka_half = (uint32_t)((g >> 1) << 4);
    const uint32_t kb_half = (uint32_t)((g & 1) << 4);
    const uint32_t rx = (uint32_t)(r << 4);

    float acc[4][4][4];
    #pragma unroll
    for (int mt = 0; mt < 4; mt++)
        #pragma unroll
        for (int nt = 0; nt < 4; nt++)
            #pragma unroll
            for (int q = 0; q < 4; q++) acc[mt][nt][q] = 0.0f;

    auto issue_load = [&](int slot, int s) {
        uint32_t base = sb + (uint32_t)slot * STAGE_B;
        int k0 = s * 64;
        #pragma unroll
        for (int q = 0; q < 4; q++) {
            uint32_t row = p_row[q];
            int gk = k0 + ((tid + q * 256) & 7) * 8;
            size_t gA = (size_t)(m0 + row) * Nn + gk;
            size_t gB = (size_t)(n0 + row) * Nn + gk;
            cp16(base + p_soff[q],          Up + gA);
            cp16(base + TILE_B + p_soff[q], Fp + gB);
        }
    };

    // double-buffered fragments
    uint32_t urb[2][4][4];
    uint32_t frb[2][2][4];

    issue_load(0, 0); CP_COMMIT();
    issue_load(1, 1); CP_COMMIT();

    int slot = 0;
    for (int s = 0; s < NSTAGE; s++) {
        CP_WAIT(1);              // stage s resident for this thread's copies
        __syncthreads();         // cross-thread visibility + frees slot (s-1)%3
        if (s + 2 < NSTAGE) issue_load((slot + 2) % NSLOT, s + 2);
        CP_COMMIT();             // uniform group accounting (empty near tail)

        uint32_t bU = sb + (uint32_t)slot * STAGE_B;
        uint32_t bF = bU + TILE_B;

        auto load_frags = [&](int bufi, int kk) {
            uint32_t ka = ((uint32_t)(kk * 32) + ka_half) ^ rx;
            uint32_t kb = ((uint32_t)(kk * 32) + kb_half) ^ rx;
            #pragma unroll
            for (int mt = 0; mt < 4; mt++)
                ldsm_x4(urb[bufi][mt], bU + arow[mt] + ka);
            #pragma unroll
            for (int p = 0; p < 2; p++)
                ldsm_x4(frb[bufi][p], bF + brow[p] + kb);
        };

        load_frags(0, 0);
        #pragma unroll
        for (int kk = 0; kk < 4; kk++) {
            int cur = kk & 1;
            if (kk < 3) load_frags(cur ^ 1, kk + 1);   // prefetch next frags
            #pragma unroll
            for (int mt = 0; mt < 4; mt++) {
                #pragma unroll
                for (int nt = 0; nt < 4; nt++) {
                    const uint32_t* fb = &frb[cur][nt >> 1][(nt & 1) * 2];
                    mma16816h(acc[mt][nt], urb[cur][mt], fb);
                }
            }
        }
        slot = (slot + 1) % NSLOT;
    }

    // ---- epilogue: out[i,c] = colsum[c] - acc ----
    float* Og = out + (size_t)b * Nn * Cc;
    const float* cs = g_colsum + b * Cc;
    const int rbase = m0 + warp_m * 64 + (lane >> 2);
    const int cbase = n0 + warp_n * 32 + (lane & 3) * 2;
    #pragma unroll
    for (int nt = 0; nt < 4; nt++) {
        int col = cbase + nt * 8;
        float cs0 = cs[col];
        float cs1 = cs[col + 1];
        #pragma unroll
        for (int mt = 0; mt < 4; mt++) {
            int row = rbase + mt * 16;
            float2 v0 = make_float2(cs0 - acc[mt][nt][0], cs1 - acc[mt][nt][1]);
            float2 v1 = make_float2(cs0 - acc[mt][nt][2], cs1 - acc[mt][nt][3]);
            *(float2*)(Og + (size_t)row * Cc + col)       = v0;
            *(float2*)(Og + (size_t)(row + 8) * Cc + col) = v1;
        }
    }
}

// ---------------- entry point ---------------------------------------------
extern "C" void kernel_launch(void* const* d_in, const int* in_sizes, int n_in,
                              void* d_out, int out_size)
{
    // metadata order: f_tar(0, unused), f_src(1), K1(2), K2(3), R(4), t(5)
    const float* f_src = (const float*)d_in[1];
    const float* K1    = (const float*)d_in[2];
    const float* K2    = (const float*)d_in[3];
    const float* R     = (const float*)d_in[4];
    const float* T     = (const float*)d_in[5];
    float* out = (float*)d_out;

    cudaFuncSetAttribute(k_gemm_mma, cudaFuncAttributeMaxDynamicSharedMemorySize, GEMM_SMEM);

    k_coef<<<Bb, 256>>>(K1, K2, R, T);
    k_row2<<<dim3(IBLK, Bb), 256>>>();
    k_cinv<<<(Bb * Nn + 255) / 256, 256>>>();
    k_conv_f<<<dim3(Cc / 4, Bb), 256>>>(f_src);
    k_gemm_mma<<<dim3(Cc / 128, Nn / 128, Bb), 256, GEMM_SMEM>>>(out);
}

// round 15
// speedup vs baseline: 1.1050x; 1.1050x over previous
#include <cuda_runtime.h>
#include <cuda_fp16.h>
#include <cstdint>
#include <math.h>

// Problem constants
#define Bb 8
#define Cc 1152
#define Hh 32
#define Ww 32
#define Nn 1024   // H*W
#define IBLK 64   // row-blocks per batch in k_row2 (Nn / ROWS_PER_BLK)

// ---------------- scratch (static device globals: allowed) ----------------
__device__ __align__(16) float g_alpha[Bb * Nn];
__device__ __align__(16) float g_beta [Bb * Nn];
__device__ __align__(16) float g_gamma[Bb * Nn];
__device__ __align__(16) float g_part [(size_t)IBLK * Bb * Nn]; // partial column sums
__device__ __align__(16) float g_cinv [Bb * Nn];                // 1 / csum
__device__ __align__(16) float g_colsum[Bb * Cc];               // colsum_c = sum_j F[c,j]
__device__ __align__(16) __half g_U[(size_t)Bb * Nn * Nn];      // u = 1 - exp(-s), fp16
__device__ __align__(16) __half g_F[(size_t)Bb * Cc * Nn];      // F = f_src / csum, fp16

// ======================= generic-PTX helpers ===============================
__device__ __forceinline__ uint32_t smem_to_u32(const void* p) {
    uint32_t a;
    asm("{ .reg .u64 t; cvta.to.shared.u64 t, %1; cvt.u32.u64 %0, t; }" : "=r"(a) : "l"(p));
    return a;
}
__device__ __forceinline__ void cp16(uint32_t s, const void* g) {
    asm volatile("cp.async.cg.shared.global [%0], [%1], 16;" :: "r"(s), "l"(g));
}
#define CP_COMMIT() asm volatile("cp.async.commit_group;" ::: "memory")
#define CP_WAIT(n)  asm volatile("cp.async.wait_group %0;" :: "n"(n) : "memory")

__device__ __forceinline__ void ldsm_x4(uint32_t* r, uint32_t addr) {
    asm volatile("ldmatrix.sync.aligned.m8n8.x4.shared.b16 {%0,%1,%2,%3}, [%4];"
                 : "=r"(r[0]), "=r"(r[1]), "=r"(r[2]), "=r"(r[3]) : "r"(addr));
}
__device__ __forceinline__ void mma16816h(float* c, const uint32_t* a, const uint32_t* b) {
    asm volatile(
        "mma.sync.aligned.m16n8k16.row.col.f32.f16.f16.f32 "
        "{%0,%1,%2,%3}, {%4,%5,%6,%7}, {%8,%9}, {%0,%1,%2,%3};"
        : "+f"(c[0]), "+f"(c[1]), "+f"(c[2]), "+f"(c[3])
        : "r"(a[0]), "r"(a[1]), "r"(a[2]), "r"(a[3]), "r"(b[0]), "r"(b[1]));
}

// ---------------- kernel 1: fundamental matrix + per-line coefficients ----
__global__ void k_coef(const float* __restrict__ K1, const float* __restrict__ K2,
                       const float* __restrict__ R,  const float* __restrict__ T)
{
    int b = blockIdx.x;
    __shared__ float F[9];
    if (threadIdx.x == 0) {
        const float* k1 = K1 + b * 9;
        const float* k2 = K2 + b * 9;
        const float* r  = R  + b * 9;
        const float* tv = T  + b * 3;
        float t0 = tv[0], t1 = tv[1], t2 = tv[2];
        float E[9];
        #pragma unroll
        for (int c = 0; c < 3; c++) {
            float r0 = r[0 * 3 + c], r1 = r[1 * 3 + c], r2 = r[2 * 3 + c];
            E[0 * 3 + c] = -t2 * r1 + t1 * r2;
            E[1 * 3 + c] =  t2 * r0 - t0 * r2;
            E[2 * 3 + c] = -t1 * r0 + t0 * r1;
        }
        float fx2 = k2[0], fy2 = k2[4], cx2 = k2[2], cy2 = k2[5];
        float M[9];
        #pragma unroll
        for (int c = 0; c < 3; c++) {
            M[0 * 3 + c] = E[0 * 3 + c] / fx2;
            M[1 * 3 + c] = E[1 * 3 + c] / fy2;
            M[2 * 3 + c] = -cx2 / fx2 * E[0 * 3 + c] - cy2 / fy2 * E[1 * 3 + c] + E[2 * 3 + c];
        }
        float fx1 = k1[0], fy1 = k1[4], cx1 = k1[2], cy1 = k1[5];
        #pragma unroll
        for (int rr = 0; rr < 3; rr++) {
            float m0 = M[rr * 3 + 0], m1 = M[rr * 3 + 1], m2 = M[rr * 3 + 2];
            F[rr * 3 + 0] = m0 / fx1;
            F[rr * 3 + 1] = m1 / fy1;
            F[rr * 3 + 2] = -cx1 / fx1 * m0 - cy1 / fy1 * m1 + m2;
        }
    }
    __syncthreads();
    for (int j = threadIdx.x; j < Nn; j += blockDim.x) {
        float x = (float)(j / Ww);
        float y = (float)(j % Ww);
        float l0 = F[0] * x + F[1] * y + F[2];
        float l1 = F[3] * x + F[4] * y + F[5];
        float l2 = F[6] * x + F[7] * y + F[8];
        float ap = l0 / l2;
        float bp = l1 / l2;
        float rn = rsqrtf(ap * ap + bp * bp);
        g_alpha[b * Nn + j] = ap * rn;
        g_beta [b * Nn + j] = bp * rn;
        g_gamma[b * Nn + j] = rn;
    }
}

// ---------------- kernel 2: warp-per-row softmax -> u = 1-exp(-s) fp16 ----
// 8 warps x 2 rows each (16 rows/block). Lane owns 32 CONSECUTIVE columns
// (lane*32..lane*32+31): coalesced 64B fp16 stores, warp-shuffle-only row
// reductions (no block sync in main loop). Coefficients staged once into
// bank-swizzled smem (addr = (j&31)*33 + (j>>5)); column-sum partials
// reduced deterministically through a swizzled smem buffer (fixed warp order).
#define ROWS_PER_BLK 16
__global__ void __launch_bounds__(256) k_row2()
{
    int b    = blockIdx.y;
    int ib   = blockIdx.x;
    int i0   = ib * ROWS_PER_BLK;
    int warp = threadIdx.x >> 5;
    int lane = threadIdx.x & 31;
    __half* Up = g_U + (size_t)b * Nn * Nn;

    __shared__ float cs_a[33 * 32];
    __shared__ float cs_b[33 * 32];
    __shared__ float cs_g[33 * 32];
    __shared__ float part_s[8][33 * 32];

    // stage coefficients, swizzled: col j at (j&31)*33 + (j>>5)
    for (int t = threadIdx.x; t < Nn; t += 256) {
        int addr = (t & 31) * 33 + (t >> 5);
        cs_a[addr] = g_alpha[b * Nn + t];
        cs_b[addr] = g_beta [b * Nn + t];
        cs_g[addr] = g_gamma[b * Nn + t];
    }
    __syncthreads();

    float cacc[32];
    #pragma unroll
    for (int q = 0; q < 32; q++) cacc[q] = 0.0f;

    #pragma unroll
    for (int r = 0; r < 2; r++) {
        int i = i0 + warp * 2 + r;
        float x = (float)(i / Ww);
        float y = (float)(i % Ww);

        float buf[32];
        float m = -1e30f;
        #pragma unroll
        for (int q = 0; q < 32; q++) {
            // col j = lane*32 + q  ->  swizzled addr q*33 + lane (bank-distinct)
            int ad = q * 33 + lane;
            float v = 5.0f * fabsf(fmaf(cs_a[ad], x, fmaf(cs_b[ad], y, cs_g[ad])));
            buf[q] = v;
            m = fmaxf(m, v);
        }
        #pragma unroll
        for (int o = 16; o; o >>= 1) m = fmaxf(m, __shfl_xor_sync(0xffffffffu, m, o));

        float z = 0.0f;
        #pragma unroll
        for (int q = 0; q < 32; q++) { buf[q] = __expf(buf[q] - m); z += buf[q]; }
        #pragma unroll
        for (int o = 16; o; o >>= 1) z += __shfl_xor_sync(0xffffffffu, z, o);
        float inv = 1.0f / z;

        // finalize: s = buf*inv, e = exp(-s), u = 1-e; pack 8 halves -> uint4
        __half* urow = Up + (size_t)i * Nn + lane * 32;
        #pragma unroll
        for (int g8 = 0; g8 < 4; g8++) {
            uint32_t w[4];
            #pragma unroll
            for (int p = 0; p < 4; p++) {
                int q0 = g8 * 8 + p * 2;
                float s0 = buf[q0]     * inv;
                float s1 = buf[q0 + 1] * inv;
                float e0 = __expf(-s0);
                float e1 = __expf(-s1);
                cacc[q0]     += e0;
                cacc[q0 + 1] += e1;
                w[p] = (uint32_t)__half_as_ushort(__float2half_rn(1.0f - e0)) |
                       ((uint32_t)__half_as_ushort(__float2half_rn(1.0f - e1)) << 16);
            }
            uint4 pk; pk.x = w[0]; pk.y = w[1]; pk.z = w[2]; pk.w = w[3];
            *(uint4*)(urow + g8 * 8) = pk;
        }
    }

    // deterministic block column-sum: warp partials to swizzled smem,
    // then each thread sums 8 warps (fixed order) for its 4 columns.
    #pragma unroll
    for (int q = 0; q < 32; q++)
        part_s[warp][q * 33 + lane] = cacc[q];   // col lane*32+q at (q,lane)
    __syncthreads();

    size_t poff = ((size_t)(b * IBLK + ib)) * Nn;
    #pragma unroll
    for (int k = 0; k < 4; k++) {
        int j  = threadIdx.x + k * 256;
        int ad = (j & 31) * 33 + (j >> 5);
        float s = 0.0f;
        #pragma unroll
        for (int w = 0; w < 8; w++) s += part_s[w][ad];
        g_part[poff + j] = s;
    }
}

// ---------------- kernel 2b: cinv = 1 / sum_ib part ------------------------
__global__ void k_cinv()
{
    int i = blockIdx.x * blockDim.x + threadIdx.x;
    if (i >= Bb * Nn) return;
    int b = i / Nn, j = i % Nn;
    float s = 0.0f;
    #pragma unroll 8
    for (int ib = 0; ib < IBLK; ib++)
        s += g_part[((size_t)(b * IBLK + ib)) * Nn + j];
    g_cinv[i] = 1.0f / s;
}

// ---------------- kernel 3: F = f/csum -> fp16; colsum_c = sum_j F (fp32) --
// (R11-proven block version: 4 c-rows/block)
__global__ void __launch_bounds__(256) k_conv_f(const float* __restrict__ f)
{
    int b  = blockIdx.y;
    int c0 = blockIdx.x * 4;
    int tid = threadIdx.x;
    const float* ci = g_cinv + b * Nn + tid * 4;
    float cv0 = ci[0], cv1 = ci[1], cv2 = ci[2], cv3 = ci[3];
    __shared__ float red[8];

    #pragma unroll
    for (int r = 0; r < 4; r++) {
        int c = c0 + r;
        size_t rowbase = ((size_t)(b * Cc + c)) * Nn;
        float4 v = *(const float4*)(f + rowbase + tid * 4);
        v.x *= cv0; v.y *= cv1; v.z *= cv2; v.w *= cv3;

        uint32_t w0 = (uint32_t)__half_as_ushort(__float2half_rn(v.x)) |
                      ((uint32_t)__half_as_ushort(__float2half_rn(v.y)) << 16);
        uint32_t w1 = (uint32_t)__half_as_ushort(__float2half_rn(v.z)) |
                      ((uint32_t)__half_as_ushort(__float2half_rn(v.w)) << 16);
        uint2 pk; pk.x = w0; pk.y = w1;
        *(uint2*)(g_F + rowbase + tid * 4) = pk;

        float sm = (v.x + v.y) + (v.z + v.w);   // fp32 colsum contribution
        #pragma unroll
        for (int o = 16; o; o >>= 1) sm += __shfl_xor_sync(0xffffffffu, sm, o);
        if ((tid & 31) == 0) red[tid >> 5] = sm;
        __syncthreads();
        if (tid == 0) {
            float t = 0.0f;
            #pragma unroll
            for (int w = 0; w < 8; w++) t += red[w];
            g_colsum[b * Cc + c] = t;
        }
        __syncthreads();
    }
}

// ---------------- kernel 4: fp16 mma GEMM, out = colsum - U @ F^T ---------
// EXACT R11 structure (proven fastest): double-buffered cp.async, 64KB SMEM,
// occupancy 2.
#define TILE_B   16384          // one 128x64 fp16 tile (swizzled, 128B rows)
#define STAGE_B  (2 * TILE_B)   // U, F
#define GEMM_SMEM (2 * STAGE_B) // 65536

__global__ void __launch_bounds__(256, 2) k_gemm_mma(float* __restrict__ out)
{
    extern __shared__ char smem[];
    const uint32_t sb = smem_to_u32(smem);
    const int tid  = threadIdx.x;
    const int wid  = tid >> 5;
    const int lane = tid & 31;
    const int b    = blockIdx.z;
    const int n0   = blockIdx.x * 128;   // c tile
    const int m0   = blockIdx.y * 128;   // i tile

    const __half* Up = g_U + (size_t)b * Nn * Nn;
    const __half* Fp = g_F + (size_t)b * Cc * Nn;

    // producer chunk mapping: 1024 16B chunks per tile, 4 per thread
    uint32_t p_soff[4];
    uint32_t p_row[4];
    #pragma unroll
    for (int q = 0; q < 4; q++) {
        int id  = tid + q * 256;
        int row = id >> 3;
        int c   = id & 7;
        p_row[q]  = row;
        p_soff[q] = (uint32_t)(row * 128 + ((16 * c) ^ ((row & 7) << 4)));
    }

    // MMA thread geometry
    const int warp_m = wid & 1;        // 0..1
    const int warp_n = wid >> 1;       // 0..3
    const int g  = lane >> 3;          // ldmatrix address group 0..3
    const int r  = lane & 7;
    uint32_t arow[4], brow[2];
    #pragma unroll
    for (int mt = 0; mt < 4; mt++)
        arow[mt] = (uint32_t)((warp_m * 64 + mt * 16 + (g & 1) * 8 + r) * 128);
    #pragma unroll
    for (int p = 0; p < 2; p++)
        brow[p] = (uint32_t)((warp_n * 32 + p * 16 + (g >> 1) * 8 + r) * 128);
    const uint32_t ka_half = (uint32_t)((g >> 1) << 4);
    const uint32_t kb_half = (uint32_t)((g & 1) << 4);
    const uint32_t rx = (uint32_t)(r << 4);

    float acc[4][4][4];
    #pragma unroll
    for (int mt = 0; mt < 4; mt++)
        #pragma unroll
        for (int nt = 0; nt < 4; nt++)
            #pragma unroll
            for (int q = 0; q < 4; q++) acc[mt][nt][q] = 0.0f;

    auto issue_load = [&](int buf, int s) {
        uint32_t base = sb + (uint32_t)buf * STAGE_B;
        int k0 = s * 64;
        #pragma unroll
        for (int q = 0; q < 4; q++) {
            uint32_t row = p_row[q];
            int gk = k0 + ((tid + q * 256) & 7) * 8;
            size_t gA = (size_t)(m0 + row) * Nn + gk;
            size_t gB = (size_t)(n0 + row) * Nn + gk;
            cp16(base + p_soff[q],          Up + gA);
            cp16(base + TILE_B + p_soff[q], Fp + gB);
        }
    };

    issue_load(0, 0);
    CP_COMMIT();

    int buf = 0;
    for (int s = 0; s < Nn / 64; s++) {
        if (s + 1 < Nn / 64) {
            issue_load(buf ^ 1, s + 1);
            CP_COMMIT();
            CP_WAIT(1);
        } else {
            CP_WAIT(0);
        }
        __syncthreads();

        uint32_t bU = sb + (uint32_t)buf * STAGE_B;
        uint32_t bF = bU + TILE_B;

        #pragma unroll
        for (int kk = 0; kk < 4; kk++) {
            uint32_t ka = ((uint32_t)(kk * 32) + ka_half) ^ rx;
            uint32_t kb = ((uint32_t)(kk * 32) + kb_half) ^ rx;
            uint32_t ur[4][4];
            #pragma unroll
            for (int mt = 0; mt < 4; mt++)
                ldsm_x4(ur[mt], bU + arow[mt] + ka);
            uint32_t fr[2][4];
            #pragma unroll
            for (int p = 0; p < 2; p++)
                ldsm_x4(fr[p], bF + brow[p] + kb);
            #pragma unroll
            for (int mt = 0; mt < 4; mt++) {
                #pragma unroll
                for (int nt = 0; nt < 4; nt++) {
                    const uint32_t* fb = &fr[nt >> 1][(nt & 1) * 2];
                    mma16816h(acc[mt][nt], ur[mt], fb);
                }
            }
        }
        __syncthreads();
        buf ^= 1;
    }

    // ---- epilogue: out[i,c] = colsum[c] - acc ----
    float* Og = out + (size_t)b * Nn * Cc;
    const float* cs = g_colsum + b * Cc;
    const int rbase = m0 + warp_m * 64 + (lane >> 2);
    const int cbase = n0 + warp_n * 32 + (lane & 3) * 2;
    #pragma unroll
    for (int nt = 0; nt < 4; nt++) {
        int col = cbase + nt * 8;
        float cs0 = cs[col];
        float cs1 = cs[col + 1];
        #pragma unroll
        for (int mt = 0; mt < 4; mt++) {
            int row = rbase + mt * 16;
            float2 v0 = make_float2(cs0 - acc[mt][nt][0], cs1 - acc[mt][nt][1]);
            float2 v1 = make_float2(cs0 - acc[mt][nt][2], cs1 - acc[mt][nt][3]);
            *(float2*)(Og + (size_t)row * Cc + col)       = v0;
            *(float2*)(Og + (size_t)(row + 8) * Cc + col) = v1;
        }
    }
}

// ---------------- entry point ---------------------------------------------
extern "C" void kernel_launch(void* const* d_in, const int* in_sizes, int n_in,
                              void* d_out, int out_size)
{
    // metadata order: f_tar(0, unused), f_src(1), K1(2), K2(3), R(4), t(5)
    const float* f_src = (const float*)d_in[1];
    const float* K1    = (const float*)d_in[2];
    const float* K2    = (const float*)d_in[3];
    const float* R     = (const float*)d_in[4];
    const float* T     = (const float*)d_in[5];
    float* out = (float*)d_out;

    cudaFuncSetAttribute(k_gemm_mma, cudaFuncAttributeMaxDynamicSharedMemorySize, GEMM_SMEM);

    k_coef<<<Bb, 256>>>(K1, K2, R, T);
    k_row2<<<dim3(IBLK, Bb), 256>>>();
    k_cinv<<<(Bb * Nn + 255) / 256, 256>>>();
    k_conv_f<<<dim3(Cc / 4, Bb), 256>>>(f_src);
    k_gemm_mma<<<dim3(Cc / 128, Nn / 128, Bb), 256, GEMM_SMEM>>>(out);
}

// round 16
// speedup vs baseline: 1.1337x; 1.0260x over previous
#include <cuda_runtime.h>
#include <cuda_fp16.h>
#include <cstdint>
#include <math.h>

// Problem constants
#define Bb 8
#define Cc 1152
#define Hh 32
#define Ww 32
#define Nn 1024   // H*W
#define IBLK 64   // row-blocks per batch in k_row2 (Nn / ROWS_PER_BLK)

// ---------------- scratch (static device globals: allowed) ----------------
__device__ __align__(16) float g_alpha[Bb * Nn];
__device__ __align__(16) float g_beta [Bb * Nn];
__device__ __align__(16) float g_gamma[Bb * Nn];
__device__ __align__(16) float g_part [(size_t)IBLK * Bb * Nn]; // partial column sums
__device__ __align__(16) float g_cinv [Bb * Nn];                // 1 / csum
__device__ __align__(16) float g_colsum[Bb * Cc];               // colsum_c = sum_j F[c,j]
__device__ __align__(16) __half g_U[(size_t)Bb * Nn * Nn];      // u = 1 - exp(-s), fp16
__device__ __align__(16) __half g_F[(size_t)Bb * Cc * Nn];      // F = f_src / csum, fp16

// ======================= generic-PTX helpers ===============================
__device__ __forceinline__ uint32_t smem_to_u32(const void* p) {
    uint32_t a;
    asm("{ .reg .u64 t; cvta.to.shared.u64 t, %1; cvt.u32.u64 %0, t; }" : "=r"(a) : "l"(p));
    return a;
}
__device__ __forceinline__ void cp16(uint32_t s, const void* g) {
    asm volatile("cp.async.cg.shared.global [%0], [%1], 16;" :: "r"(s), "l"(g));
}
#define CP_COMMIT() asm volatile("cp.async.commit_group;" ::: "memory")
#define CP_WAIT(n)  asm volatile("cp.async.wait_group %0;" :: "n"(n) : "memory")

__device__ __forceinline__ void ldsm_x4(uint32_t* r, uint32_t addr) {
    asm volatile("ldmatrix.sync.aligned.m8n8.x4.shared.b16 {%0,%1,%2,%3}, [%4];"
                 : "=r"(r[0]), "=r"(r[1]), "=r"(r[2]), "=r"(r[3]) : "r"(addr));
}
__device__ __forceinline__ void mma16816h(float* c, const uint32_t* a, const uint32_t* b) {
    asm volatile(
        "mma.sync.aligned.m16n8k16.row.col.f32.f16.f16.f32 "
        "{%0,%1,%2,%3}, {%4,%5,%6,%7}, {%8,%9}, {%0,%1,%2,%3};"
        : "+f"(c[0]), "+f"(c[1]), "+f"(c[2]), "+f"(c[3])
        : "r"(a[0]), "r"(a[1]), "r"(a[2]), "r"(a[3]), "r"(b[0]), "r"(b[1]));
}

// ---------------- kernel 1: fundamental matrix + per-line coefficients ----
__global__ void k_coef(const float* __restrict__ K1, const float* __restrict__ K2,
                       const float* __restrict__ R,  const float* __restrict__ T)
{
    int b = blockIdx.x;
    __shared__ float F[9];
    if (threadIdx.x == 0) {
        const float* k1 = K1 + b * 9;
        const float* k2 = K2 + b * 9;
        const float* r  = R  + b * 9;
        const float* tv = T  + b * 3;
        float t0 = tv[0], t1 = tv[1], t2 = tv[2];
        float E[9];
        #pragma unroll
        for (int c = 0; c < 3; c++) {
            float r0 = r[0 * 3 + c], r1 = r[1 * 3 + c], r2 = r[2 * 3 + c];
            E[0 * 3 + c] = -t2 * r1 + t1 * r2;
            E[1 * 3 + c] =  t2 * r0 - t0 * r2;
            E[2 * 3 + c] = -t1 * r0 + t0 * r1;
        }
        float fx2 = k2[0], fy2 = k2[4], cx2 = k2[2], cy2 = k2[5];
        float M[9];
        #pragma unroll
        for (int c = 0; c < 3; c++) {
            M[0 * 3 + c] = E[0 * 3 + c] / fx2;
            M[1 * 3 + c] = E[1 * 3 + c] / fy2;
            M[2 * 3 + c] = -cx2 / fx2 * E[0 * 3 + c] - cy2 / fy2 * E[1 * 3 + c] + E[2 * 3 + c];
        }
        float fx1 = k1[0], fy1 = k1[4], cx1 = k1[2], cy1 = k1[5];
        #pragma unroll
        for (int rr = 0; rr < 3; rr++) {
            float m0 = M[rr * 3 + 0], m1 = M[rr * 3 + 1], m2 = M[rr * 3 + 2];
            F[rr * 3 + 0] = m0 / fx1;
            F[rr * 3 + 1] = m1 / fy1;
            F[rr * 3 + 2] = -cx1 / fx1 * m0 - cy1 / fy1 * m1 + m2;
        }
    }
    __syncthreads();
    for (int j = threadIdx.x; j < Nn; j += blockDim.x) {
        float x = (float)(j / Ww);
        float y = (float)(j % Ww);
        float l0 = F[0] * x + F[1] * y + F[2];
        float l1 = F[3] * x + F[4] * y + F[5];
        float l2 = F[6] * x + F[7] * y + F[8];
        float ap = l0 / l2;
        float bp = l1 / l2;
        float rn = rsqrtf(ap * ap + bp * bp);
        g_alpha[b * Nn + j] = ap * rn;
        g_beta [b * Nn + j] = bp * rn;
        g_gamma[b * Nn + j] = rn;
    }
}

// ---------------- kernel 2: fused row-softmax -> u = 1-exp(-s) fp16 ------
// (R11-proven block version)
#define ROWS_PER_BLK 16
__global__ void __launch_bounds__(256) k_row2()
{
    int b  = blockIdx.y;
    int ib = blockIdx.x;
    int i0 = ib * ROWS_PER_BLK;
    const float* al = g_alpha + b * Nn;
    const float* be = g_beta  + b * Nn;
    const float* ga = g_gamma + b * Nn;
    __half* Up = g_U + (size_t)b * Nn * Nn;

    __shared__ float redm[8];
    __shared__ float redz[8];

    float A4[4], B4[4], G4[4];
    float cacc[4];
    #pragma unroll
    for (int k = 0; k < 4; k++) {
        int j = threadIdx.x + k * 256;
        A4[k] = al[j]; B4[k] = be[j]; G4[k] = ga[j];
        cacc[k] = 0.0f;
    }

    for (int r = 0; r < ROWS_PER_BLK; r++) {
        int i = i0 + r;
        float x = (float)(i / Ww);
        float y = (float)(i % Ww);
        float v[4];
        float m = -1e30f;
        #pragma unroll
        for (int k = 0; k < 4; k++) {
            v[k] = 5.0f * fabsf(fmaf(A4[k], x, fmaf(B4[k], y, G4[k])));
            m = fmaxf(m, v[k]);
        }
        #pragma unroll
        for (int o = 16; o; o >>= 1) m = fmaxf(m, __shfl_xor_sync(0xffffffffu, m, o));
        if ((threadIdx.x & 31) == 0) redm[threadIdx.x >> 5] = m;
        __syncthreads();
        float bm = redm[0];
        #pragma unroll
        for (int w = 1; w < 8; w++) bm = fmaxf(bm, redm[w]);

        float e1[4];
        float z = 0.0f;
        #pragma unroll
        for (int k = 0; k < 4; k++) { e1[k] = __expf(v[k] - bm); z += e1[k]; }
        #pragma unroll
        for (int o = 16; o; o >>= 1) z += __shfl_xor_sync(0xffffffffu, z, o);
        if ((threadIdx.x & 31) == 0) redz[threadIdx.x >> 5] = z;
        __syncthreads();
        float bz = 0.0f;
        #pragma unroll
        for (int w = 0; w < 8; w++) bz += redz[w];
        float inv = 1.0f / bz;

        size_t rowoff = (size_t)i * Nn;   // batch offset lives in Up pointer
        #pragma unroll
        for (int k = 0; k < 4; k++) {
            float s = e1[k] * inv;               // row-softmax value in (0,1]
            float e = __expf(-s);                // column-softmax numerator (shift 0)
            cacc[k] += e;
            float u = 1.0f - e;                  // GEMM operand: out = colsum - U@F^T
            int j = threadIdx.x + k * 256;
            Up[rowoff + j] = __float2half_rn(u);
        }
    }

    size_t poff = ((size_t)(b * IBLK + ib)) * Nn;
    #pragma unroll
    for (int k = 0; k < 4; k++)
        g_part[poff + threadIdx.x + k * 256] = cacc[k];
}

// ---------------- kernel 2b: cinv = 1 / sum_ib part ------------------------
__global__ void k_cinv()
{
    int i = blockIdx.x * blockDim.x + threadIdx.x;
    if (i >= Bb * Nn) return;
    int b = i / Nn, j = i % Nn;
    float s = 0.0f;
    #pragma unroll 8
    for (int ib = 0; ib < IBLK; ib++)
        s += g_part[((size_t)(b * IBLK + ib)) * Nn + j];
    g_cinv[i] = 1.0f / s;
}

// ---------------- kernel 3: F = f/csum -> fp16; colsum_c = sum_j F (fp32) --
// 4 c-rows/block (R11 structure). Changes vs R11: packed f16x2 converts
// (__floats2half2_rn -> guaranteed paired F2FP), and row reductions deferred
// into red[4][8] so the block does 2 barriers instead of 8.
__global__ void __launch_bounds__(256) k_conv_f(const float* __restrict__ f)
{
    int b  = blockIdx.y;
    int c0 = blockIdx.x * 4;
    int tid = threadIdx.x;
    const float* ci = g_cinv + b * Nn + tid * 4;
    float cv0 = ci[0], cv1 = ci[1], cv2 = ci[2], cv3 = ci[3];
    __shared__ float red[4][8];

    #pragma unroll
    for (int r = 0; r < 4; r++) {
        int c = c0 + r;
        size_t rowbase = ((size_t)(b * Cc + c)) * Nn;
        float4 v = *(const float4*)(f + rowbase + tid * 4);
        v.x *= cv0; v.y *= cv1; v.z *= cv2; v.w *= cv3;

        __half2 h0 = __floats2half2_rn(v.x, v.y);
        __half2 h1 = __floats2half2_rn(v.z, v.w);
        uint2 pk;
        pk.x = *(const uint32_t*)&h0;
        pk.y = *(const uint32_t*)&h1;
        *(uint2*)(g_F + rowbase + tid * 4) = pk;

        float sm = (v.x + v.y) + (v.z + v.w);   // fp32 colsum contribution
        #pragma unroll
        for (int o = 16; o; o >>= 1) sm += __shfl_xor_sync(0xffffffffu, sm, o);
        if ((tid & 31) == 0) red[r][tid >> 5] = sm;
    }
    __syncthreads();
    if (tid < 4) {
        float t = 0.0f;
        #pragma unroll
        for (int w = 0; w < 8; w++) t += red[tid][w];
        g_colsum[b * Cc + c0 + tid] = t;
    }
}

// ---------------- kernel 4: fp16 mma GEMM, out = colsum - U @ F^T ---------
// EXACT R11 structure (proven fastest): double-buffered cp.async, 64KB SMEM,
// occupancy 2.
#define TILE_B   16384          // one 128x64 fp16 tile (swizzled, 128B rows)
#define STAGE_B  (2 * TILE_B)   // U, F
#define GEMM_SMEM (2 * STAGE_B) // 65536

__global__ void __launch_bounds__(256, 2) k_gemm_mma(float* __restrict__ out)
{
    extern __shared__ char smem[];
    const uint32_t sb = smem_to_u32(smem);
    const int tid  = threadIdx.x;
    const int wid  = tid >> 5;
    const int lane = tid & 31;
    const int b    = blockIdx.z;
    const int n0   = blockIdx.x * 128;   // c tile
    const int m0   = blockIdx.y * 128;   // i tile

    const __half* Up = g_U + (size_t)b * Nn * Nn;
    const __half* Fp = g_F + (size_t)b * Cc * Nn;

    // producer chunk mapping: 1024 16B chunks per tile, 4 per thread
    uint32_t p_soff[4];
    uint32_t p_row[4];
    #pragma unroll
    for (int q = 0; q < 4; q++) {
        int id  = tid + q * 256;
        int row = id >> 3;
        int c   = id & 7;
        p_row[q]  = row;
        p_soff[q] = (uint32_t)(row * 128 + ((16 * c) ^ ((row & 7) << 4)));
    }

    // MMA thread geometry
    const int warp_m = wid & 1;        // 0..1
    const int warp_n = wid >> 1;       // 0..3
    const int g  = lane >> 3;          // ldmatrix address group 0..3
    const int r  = lane & 7;
    uint32_t arow[4], brow[2];
    #pragma unroll
    for (int mt = 0; mt < 4; mt++)
        arow[mt] = (uint32_t)((warp_m * 64 + mt * 16 + (g & 1) * 8 + r) * 128);
    #pragma unroll
    for (int p = 0; p < 2; p++)
        brow[p] = (uint32_t)((warp_n * 32 + p * 16 + (g >> 1) * 8 + r) * 128);
    const uint32_t ka_half = (uint32_t)((g >> 1) << 4);
    const uint32_t kb_half = (uint32_t)((g & 1) << 4);
    const uint32_t rx = (uint32_t)(r << 4);

    float acc[4][4][4];
    #pragma unroll
    for (int mt = 0; mt < 4; mt++)
        #pragma unroll
        for (int nt = 0; nt < 4; nt++)
            #pragma unroll
            for (int q = 0; q < 4; q++) acc[mt][nt][q] = 0.0f;

    auto issue_load = [&](int buf, int s) {
        uint32_t base = sb + (uint32_t)buf * STAGE_B;
        int k0 = s * 64;
        #pragma unroll
        for (int q = 0; q < 4; q++) {
            uint32_t row = p_row[q];
            int gk = k0 + ((tid + q * 256) & 7) * 8;
            size_t gA = (size_t)(m0 + row) * Nn + gk;
            size_t gB = (size_t)(n0 + row) * Nn + gk;
            cp16(base + p_soff[q],          Up + gA);
            cp16(base + TILE_B + p_soff[q], Fp + gB);
        }
    };

    issue_load(0, 0);
    CP_COMMIT();

    int buf = 0;
    for (int s = 0; s < Nn / 64; s++) {
        if (s + 1 < Nn / 64) {
            issue_load(buf ^ 1, s + 1);
            CP_COMMIT();
            CP_WAIT(1);
        } else {
            CP_WAIT(0);
        }
        __syncthreads();

        uint32_t bU = sb + (uint32_t)buf * STAGE_B;
        uint32_t bF = bU + TILE_B;

        #pragma unroll
        for (int kk = 0; kk < 4; kk++) {
            uint32_t ka = ((uint32_t)(kk * 32) + ka_half) ^ rx;
            uint32_t kb = ((uint32_t)(kk * 32) + kb_half) ^ rx;
            uint32_t ur[4][4];
            #pragma unroll
            for (int mt = 0; mt < 4; mt++)
                ldsm_x4(ur[mt], bU + arow[mt] + ka);
            uint32_t fr[2][4];
            #pragma unroll
            for (int p = 0; p < 2; p++)
                ldsm_x4(fr[p], bF + brow[p] + kb);
            #pragma unroll
            for (int mt = 0; mt < 4; mt++) {
                #pragma unroll
                for (int nt = 0; nt < 4; nt++) {
                    const uint32_t* fb = &fr[nt >> 1][(nt & 1) * 2];
                    mma16816h(acc[mt][nt], ur[mt], fb);
                }
            }
        }
        __syncthreads();
        buf ^= 1;
    }

    // ---- epilogue: out[i,c] = colsum[c] - acc ----
    float* Og = out + (size_t)b * Nn * Cc;
    const float* cs = g_colsum + b * Cc;
    const int rbase = m0 + warp_m * 64 + (lane >> 2);
    const int cbase = n0 + warp_n * 32 + (lane & 3) * 2;
    #pragma unroll
    for (int nt = 0; nt < 4; nt++) {
        int col = cbase + nt * 8;
        float cs0 = cs[col];
        float cs1 = cs[col + 1];
        #pragma unroll
        for (int mt = 0; mt < 4; mt++) {
            int row = rbase + mt * 16;
            float2 v0 = make_float2(cs0 - acc[mt][nt][0], cs1 - acc[mt][nt][1]);
            float2 v1 = make_float2(cs0 - acc[mt][nt][2], cs1 - acc[mt][nt][3]);
            *(float2*)(Og + (size_t)row * Cc + col)       = v0;
            *(float2*)(Og + (size_t)(row + 8) * Cc + col) = v1;
        }
    }
}

// ---------------- entry point ---------------------------------------------
extern "C" void kernel_launch(void* const* d_in, const int* in_sizes, int n_in,
                              void* d_out, int out_size)
{
    // metadata order: f_tar(0, unused), f_src(1), K1(2), K2(3), R(4), t(5)
    const float* f_src = (const float*)d_in[1];
    const float* K1    = (const float*)d_in[2];
    const float* K2    = (const float*)d_in[3];
    const float* R     = (const float*)d_in[4];
    const float* T     = (const float*)d_in[5];
    float* out = (float*)d_out;

    cudaFuncSetAttribute(k_gemm_mma, cudaFuncAttributeMaxDynamicSharedMemorySize, GEMM_SMEM);

    k_coef<<<Bb, 256>>>(K1, K2, R, T);
    k_row2<<<dim3(IBLK, Bb), 256>>>();
    k_cinv<<<(Bb * Nn + 255) / 256, 256>>>();
    k_conv_f<<<dim3(Cc / 4, Bb), 256>>>(f_src);
    k_gemm_mma<<<dim3(Cc / 128, Nn / 128, Bb), 256, GEMM_SMEM>>>(out);
}